// round 5
// baseline (speedup 1.0000x reference)
#include <cuda_runtime.h>
#include <math.h>

// Problem constants
constexpr int CB = 512;        // batch
constexpr int CK = 25;         // nodes per board (incl. anchor node 0)
constexpr int CH = 256;        // hidden
constexpr int CSTEPS = 32;
constexpr int CN = CB * CK;    // 12800 nodes
constexpr int CNH = CN * CH;   // 3276800

// Scratch (device globals; no allocation allowed)
__device__ float g_x[CNH];             // lstm_emb (constant x)
__device__ float g_h[CNH];             // hidden state
__device__ float g_c[CNH];             // cell state
__device__ float g_gx[CN * 1024];      // chain prefix: x @ W_ih[:, :256].T
__device__ float g_A[CNH];             // per-step A = h @ W1^T (edge-chain first half)
__device__ float g_m[CNH];             // per-step messages
__device__ float g_gates[CN * 1024];   // gates
__device__ float g_W2T[256 * 256];     // W2 transposed: W2T[k*256+r] = Wmsg[r*512 + 256 + k]
__device__ float g_oe[CNH];            // output_embeddings
__device__ float g_red[CSTEPS * CB + CB];  // per-block gol partials

// ---------------------------------------------------------------------------
// XLA elementwise replicas (EmitFastTanh; logistic = 0.5 + 0.5*tanh(0.5x)).
__device__ __forceinline__ float xla_tanh(float x)
{
    float xc = fminf(fmaxf(x, -9.f), 9.f);
    float x2 = __fmul_rn(xc, xc);
    float np = fmaf(x2, -2.76076847742355e-16f, 2.00018790482477e-13f);
    np = fmaf(x2, np, -8.60467152213735e-11f);
    np = fmaf(x2, np,  5.12229709037114e-08f);
    np = fmaf(x2, np,  1.48572235717979e-05f);
    np = fmaf(x2, np,  6.37261928875436e-04f);
    np = fmaf(x2, np,  4.89352455891786e-03f);
    float num = __fmul_rn(xc, np);
    float dp = fmaf(x2, 1.19825839466702e-06f, 1.18534705686654e-04f);
    dp = fmaf(x2, dp, 2.26843463243900e-03f);
    dp = fmaf(x2, dp, 4.89352518554385e-03f);
    float r = __fdiv_rn(num, dp);
    return (fabsf(x) < 0.0004f) ? x : r;
}
__device__ __forceinline__ float xla_sigmoid(float x)
{
    return __fadd_rn(0.5f, __fmul_rn(0.5f, xla_tanh(__fmul_rn(0.5f, x))));
}

// ---------------------------------------------------------------------------
// Transpose W2 for coalesced access in msg_exact
__global__ void prep_kernel(const float* __restrict__ Wmsg)
{
    int t = blockIdx.x * blockDim.x + threadIdx.x;
    if (t >= 256 * 256) return;
    int k = t >> 8, r = t & 255;
    g_W2T[k * 256 + r] = Wmsg[r * 512 + 256 + k];
}

// ---------------------------------------------------------------------------
// x = emb[perm]; h0=c0=x; write lstm_emb output; zero anchor-node message rows
__global__ void gather_init(const float* __restrict__ emb,
                            const int* __restrict__ perm,
                            float* __restrict__ out_lstm_emb)
{
    int gid = blockIdx.x * blockDim.x + threadIdx.x;
    if (gid >= CNH) return;
    int n = gid >> 8, h = gid & 255;
    float v = emb[(size_t)perm[n] * CH + h];
    g_x[gid] = v;
    out_lstm_emb[gid] = v;
    g_h[gid] = v;
    g_c[gid] = v;
    if (n % CK == 0) g_m[gid] = 0.f;   // node 0 never receives messages
}

// ---------------------------------------------------------------------------
// C[M,N] = A[M,K] @ B[N,K]^T. Each output is ONE sequential fma chain over k
// (matches cuBLAS SGEMM association).
// mode 0: acc starts at 0, store acc.
// mode 1: acc starts at 0, store acc + Cinit   (post-add, commutative w/ ref)
// mode 2: acc starts at Cinit (chain prefix), store acc.
__global__ __launch_bounds__(256, 2) void sgemm_nt(
    int M, int N, int K,
    const float* __restrict__ A, int lda,
    const float* __restrict__ Bm, int ldb,
    float* __restrict__ C, int ldc,
    const float* __restrict__ Cinit, int mode)
{
    __shared__ float As[16][128];
    __shared__ float Bs[16][128];
    const int tid = threadIdx.x;
    const int tx = tid & 15;
    const int ty = tid >> 4;
    const float* Ab = A + (size_t)blockIdx.y * 128 * lda;
    const float* Bb = Bm + (size_t)blockIdx.x * 128 * ldb;

    float acc[8][8];
    if (mode == 2) {
#pragma unroll
        for (int i = 0; i < 8; i++) {
            int lr = (i < 4) ? (ty * 4 + i) : (64 + ty * 4 + i - 4);
            size_t r = (size_t)blockIdx.y * 128 + lr;
            const float* Ir = Cinit + r * ldc + (size_t)blockIdx.x * 128;
            float4 c0 = *(const float4*)(Ir + tx * 4);
            float4 c1 = *(const float4*)(Ir + 64 + tx * 4);
            acc[i][0] = c0.x; acc[i][1] = c0.y; acc[i][2] = c0.z; acc[i][3] = c0.w;
            acc[i][4] = c1.x; acc[i][5] = c1.y; acc[i][6] = c1.z; acc[i][7] = c1.w;
        }
    } else {
#pragma unroll
        for (int i = 0; i < 8; i++)
#pragma unroll
            for (int j = 0; j < 8; j++) acc[i][j] = 0.f;
    }

    const int lrow = tid >> 1;
    const int lk4b = (tid & 1) * 2;

    for (int kt = 0; kt < K; kt += 16) {
#pragma unroll
        for (int u = 0; u < 2; u++) {
            int k4 = lk4b + u;
            float4 av = *(const float4*)(Ab + (size_t)lrow * lda + kt + k4 * 4);
            As[k4 * 4 + 0][lrow] = av.x;
            As[k4 * 4 + 1][lrow] = av.y;
            As[k4 * 4 + 2][lrow] = av.z;
            As[k4 * 4 + 3][lrow] = av.w;
            float4 bv = *(const float4*)(Bb + (size_t)lrow * ldb + kt + k4 * 4);
            Bs[k4 * 4 + 0][lrow] = bv.x;
            Bs[k4 * 4 + 1][lrow] = bv.y;
            Bs[k4 * 4 + 2][lrow] = bv.z;
            Bs[k4 * 4 + 3][lrow] = bv.w;
        }
        __syncthreads();
#pragma unroll
        for (int k = 0; k < 16; k++) {
            float a[8], b[8];
            *(float4*)(a)     = *(const float4*)(&As[k][ty * 4]);
            *(float4*)(a + 4) = *(const float4*)(&As[k][64 + ty * 4]);
            *(float4*)(b)     = *(const float4*)(&Bs[k][tx * 4]);
            *(float4*)(b + 4) = *(const float4*)(&Bs[k][64 + tx * 4]);
#pragma unroll
            for (int i = 0; i < 8; i++)
#pragma unroll
                for (int j = 0; j < 8; j++)
                    acc[i][j] = fmaf(a[i], b[j], acc[i][j]);
        }
        __syncthreads();
    }

#pragma unroll
    for (int i = 0; i < 8; i++) {
        int lr = (i < 4) ? (ty * 4 + i) : (64 + ty * 4 + i - 4);
        size_t r = (size_t)blockIdx.y * 128 + lr;
        float* Cr = C + r * ldc + (size_t)blockIdx.x * 128;
        float4 v0 = make_float4(acc[i][0], acc[i][1], acc[i][2], acc[i][3]);
        float4 v1 = make_float4(acc[i][4], acc[i][5], acc[i][6], acc[i][7]);
        if (mode == 1) {
            const float* Ir = Cinit + r * ldc + (size_t)blockIdx.x * 128;
            float4 c0 = *(const float4*)(Ir + tx * 4);
            float4 c1 = *(const float4*)(Ir + 64 + tx * 4);
            v0.x = __fadd_rn(v0.x, c0.x); v0.y = __fadd_rn(v0.y, c0.y);
            v0.z = __fadd_rn(v0.z, c0.z); v0.w = __fadd_rn(v0.w, c0.w);
            v1.x = __fadd_rn(v1.x, c1.x); v1.y = __fadd_rn(v1.y, c1.y);
            v1.z = __fadd_rn(v1.z, c1.z); v1.w = __fadd_rn(v1.w, c1.w);
        }
        *(float4*)(Cr + tx * 4) = v0;
        *(float4*)(Cr + 64 + tx * 4) = v1;
    }
}

// ---------------------------------------------------------------------------
// Exact per-edge msg chains. Block = (dst j, board b); thread = output r.
// Edge (i -> j): acc starts at A_i[r] (chain over h_src terms, precomputed),
// then continues the SAME fma chain over the h_dst terms:
//   acc = fma(h_j[k], W2[r,k], acc), k ascending.
// Then m_j[r] = sum over ascending i (i != j) of relu(acc_i).
__global__ __launch_bounds__(256) void msg_exact()
{
    __shared__ float hj[256];
    const int j = blockIdx.x;          // dst 0..23 -> node base+j
    const int b = blockIdx.y;
    const int base = b * CK + 1;
    const int r = threadIdx.x;

    hj[r] = g_h[(size_t)(base + j) * CH + r];
    __syncthreads();

    float acc[24];
#pragma unroll
    for (int i = 0; i < 24; i++)
        acc[i] = g_A[(size_t)(base + i) * CH + r];

#pragma unroll 4
    for (int k = 0; k < 256; k++) {
        float w = g_W2T[k * 256 + r];
        float hk = hj[k];
#pragma unroll
        for (int i = 0; i < 24; i++)
            acc[i] = fmaf(hk, w, acc[i]);
    }

    float m = 0.f;
#pragma unroll
    for (int i = 0; i < 24; i++)
        if (i != j) m = __fadd_rn(m, fmaxf(acc[i], 0.f));
    g_m[(size_t)(base + j) * CH + r] = m;
}

// ---------------------------------------------------------------------------
// LSTM pointwise (explicit rn mul/add: XLA emits separate mul/add, no fma)
__global__ void lstm_step(float* __restrict__ hs_slice)
{
    int gid = blockIdx.x * blockDim.x + threadIdx.x;
    if (gid >= CNH) return;
    int n = gid >> 8, h = gid & 255;
    const float* g = g_gates + (size_t)n * 1024;
    float ig = g[h], fg = g[256 + h], gg = g[512 + h], og = g[768 + h];
    float c = g_c[gid];
    float si = xla_sigmoid(ig);
    float sf = xla_sigmoid(fg);
    float so = xla_sigmoid(og);
    float nc = __fadd_rn(__fmul_rn(sf, c), __fmul_rn(si, xla_tanh(gg)));
    float nh = __fmul_rn(so, xla_tanh(nc));
    g_c[gid] = nc;
    g_h[gid] = nh;
    hs_slice[gid] = nh;
}

// ---------------------------------------------------------------------------
// input_emb_out / output_emb_out assembly
__global__ void finalize_emb(float* __restrict__ o_in, float* __restrict__ o_out)
{
    int gid = blockIdx.x * blockDim.x + threadIdx.x;
    if (gid >= CNH) return;
    int n = gid >> 8;
    bool anchor = (n % CK) == 0;
    float xv = g_x[gid];
    float hv = g_h[gid];
    float ov = g_oe[gid];
    o_in[gid]  = anchor ? xv : hv;
    o_out[gid] = anchor ? xv : ov;
}

// ---------------------------------------------------------------------------
// avg_dot over one 24x256 group
__global__ __launch_bounds__(256) void gol_kernel(const float* __restrict__ src, int out_base)
{
    __shared__ float hn[24][257];
    __shared__ float nrm[24];
    __shared__ float red[256];
    const int tid = threadIdx.x;
    const size_t rowbase = (size_t)blockIdx.x * 25 + 1;
    for (int idx = tid; idx < 24 * 256; idx += 256) {
        int i = idx >> 8, k = idx & 255;
        hn[i][k] = src[(rowbase + i) * 256 + k];
    }
    __syncthreads();
    if (tid < 24) {
        float s = 0.f;
        for (int k = 0; k < 256; k++) { float v = hn[tid][k]; s += v * v; }
        nrm[tid] = 1.f / (sqrtf(s) + 1e-8f);
    }
    __syncthreads();
    for (int idx = tid; idx < 24 * 256; idx += 256) {
        int i = idx >> 8, k = idx & 255;
        hn[i][k] *= nrm[i];
    }
    __syncthreads();
    float local = 0.f;
    for (int p = tid; p < 276; p += 256) {
        int i = 0, pp = p;
        while (pp >= 23 - i) { pp -= 23 - i; i++; }
        int j = i + 1 + pp;
        float d = 0.f;
#pragma unroll 8
        for (int k = 0; k < 256; k++) d += hn[i][k] * hn[j][k];
        local += fabsf(d);
    }
    red[tid] = local;
    __syncthreads();
    for (int s = 128; s > 0; s >>= 1) {
        if (tid < s) red[tid] += red[tid + s];
        __syncthreads();
    }
    if (tid == 0) g_red[out_base + blockIdx.x] = red[0] * (2.f / (24.f * 23.f));
}

__global__ void gol_finalize(float* __restrict__ out)
{
    __shared__ double red[256];
    int tid = threadIdx.x;
    double s1 = 0.0, s2 = 0.0;
    for (int i = tid; i < CSTEPS * CB; i += 256) s1 += (double)g_red[i];
    for (int i = tid; i < CB; i += 256) s2 += (double)g_red[CSTEPS * CB + i];
    red[tid] = s1 / (double)(CSTEPS * CB) + s2 / (double)CB;
    __syncthreads();
    for (int s = 128; s > 0; s >>= 1) {
        if (tid < s) red[tid] += red[tid + s];
        __syncthreads();
    }
    if (tid == 0) out[0] = (float)red[0];
}

// ---------------------------------------------------------------------------
extern "C" void kernel_launch(void* const* d_in, const int* in_sizes, int n_in,
                              void* d_out, int out_size)
{
    (void)in_sizes; (void)n_in; (void)out_size;
    const float* emb  = (const float*)d_in[0];  // fixed_embeddings (65,256)
    const float* Wmsg = (const float*)d_in[1];  // (256,512)
    const float* Wih  = (const float*)d_in[2];  // (1024,512)
    const float* Whh  = (const float*)d_in[3];  // (1024,256)
    const float* Wout = (const float*)d_in[4];  // (256,256)
    const int*   perm = (const int*)d_in[5];    // (512,25)

    float* out = (float*)d_out;
    float* o_gol  = out;
    float* o_lstm = out + 1;
    float* o_in   = out + 1 + (size_t)CNH;
    float* o_out  = out + 1 + 2 * (size_t)CNH;
    float* o_hs   = out + 1 + 3 * (size_t)CNH;

    float *px, *ph, *pgx, *pA, *pm, *pgates, *poe;
    cudaGetSymbolAddress((void**)&px,     g_x);
    cudaGetSymbolAddress((void**)&ph,     g_h);
    cudaGetSymbolAddress((void**)&pgx,    g_gx);
    cudaGetSymbolAddress((void**)&pA,     g_A);
    cudaGetSymbolAddress((void**)&pm,     g_m);
    cudaGetSymbolAddress((void**)&pgates, g_gates);
    cudaGetSymbolAddress((void**)&poe,    g_oe);

    prep_kernel<<<256, 256>>>(Wmsg);
    gather_init<<<CNH / 256, 256>>>(emb, perm, o_lstm);

    // gx = x @ W_ih[:, :256]^T  — chain prefix of t1, bitwise reusable each step
    sgemm_nt<<<dim3(8, CN / 128), 256>>>(CN, 1024, 256, px, 256, Wih, 512,
                                         pgx, 1024, nullptr, 0);

    for (int s = 0; s < CSTEPS; s++) {
        // A = h @ W1^T  (edge-chain first half; W1 = Wmsg[:, :256], ldb=512)
        sgemm_nt<<<dim3(2, CN / 128), 256>>>(CN, 256, 256, ph, 256, Wmsg, 512,
                                             pA, 256, nullptr, 0);
        // per-edge chain continuation + relu + ascending-i sum
        msg_exact<<<dim3(24, CB), 256>>>();
        // t1 = [x|m]@W_ih^T == chain(m-part) with acc initialized to gx (mode 2)
        sgemm_nt<<<dim3(8, CN / 128), 256>>>(CN, 1024, 256, pm, 256, Wih + 256, 512,
                                             pgates, 1024, pgx, 2);
        // gates = t1 + t2, t2 = h@W_hh^T (full chain from 0, post-add t1; mode 1)
        sgemm_nt<<<dim3(8, CN / 128), 256>>>(CN, 1024, 256, ph, 256, Whh, 256,
                                             pgates, 1024, pgates, 1);
        lstm_step<<<CNH / 256, 256>>>(o_hs + (size_t)s * CNH);
    }

    // output_embeddings = h_last @ W_out^T
    sgemm_nt<<<dim3(2, CN / 128), 256>>>(CN, 256, 256, ph, 256, Wout, 256,
                                         poe, 256, nullptr, 0);
    finalize_emb<<<CNH / 256, 256>>>(o_in, o_out);

    gol_kernel<<<CSTEPS * CB, 256>>>(o_hs, 0);
    gol_kernel<<<CB, 256>>>(poe, CSTEPS * CB);
    gol_finalize<<<1, 256>>>(o_gol);
}

// round 6
// speedup vs baseline: 1.0638x; 1.0638x over previous
#include <cuda_runtime.h>
#include <math.h>

// Problem constants
constexpr int CB = 512;        // batch
constexpr int CK = 25;         // nodes per board (incl. anchor node 0)
constexpr int CH = 256;        // hidden
constexpr int CSTEPS = 32;
constexpr int CN = CB * CK;    // 12800 nodes
constexpr int CNH = CN * CH;   // 3276800

// Scratch (device globals; no allocation allowed)
__device__ float g_x[CNH];             // lstm_emb (constant x)
__device__ float g_h[CNH];             // hidden state
__device__ float g_c[CNH];             // cell state
__device__ float g_gx[CN * 1024];      // chain prefix: x @ W_ih[:, :256].T
__device__ float g_A[CNH];             // per-step A = h @ W1^T (edge-chain first half)
__device__ float g_m[CNH];             // per-step messages
__device__ float g_gates[CN * 1024];   // gates
__device__ float g_W2T[256 * 256];     // W2 transposed: W2T[k*256+r] = Wmsg[r*512 + 256 + k]
__device__ float g_oe[CNH];            // output_embeddings
__device__ float g_red[CSTEPS * CB + CB];  // per-block gol partials

// ---------------------------------------------------------------------------
// Packed f32x2 helpers (Blackwell FFMA2). Each lane is an independent IEEE
// round-to-nearest fp32 FMA — BITWISE identical to scalar fmaf, 2x throughput.
typedef unsigned long long u64;
__device__ __forceinline__ u64 pk2(float lo, float hi)
{
    u64 r; asm("mov.b64 %0, {%1, %2};" : "=l"(r) : "f"(lo), "f"(hi)); return r;
}
__device__ __forceinline__ float2 up2(u64 v)
{
    float2 f; asm("mov.b64 {%0, %1}, %2;" : "=f"(f.x), "=f"(f.y) : "l"(v)); return f;
}
__device__ __forceinline__ u64 ffma2(u64 a, u64 b, u64 c)
{
    u64 d; asm("fma.rn.f32x2 %0, %1, %2, %3;" : "=l"(d) : "l"(a), "l"(b), "l"(c));
    return d;
}

// ---------------------------------------------------------------------------
// XLA elementwise replicas (EmitFastTanh; logistic = 0.5 + 0.5*tanh(0.5x)).
__device__ __forceinline__ float xla_tanh(float x)
{
    float xc = fminf(fmaxf(x, -9.f), 9.f);
    float x2 = __fmul_rn(xc, xc);
    float np = fmaf(x2, -2.76076847742355e-16f, 2.00018790482477e-13f);
    np = fmaf(x2, np, -8.60467152213735e-11f);
    np = fmaf(x2, np,  5.12229709037114e-08f);
    np = fmaf(x2, np,  1.48572235717979e-05f);
    np = fmaf(x2, np,  6.37261928875436e-04f);
    np = fmaf(x2, np,  4.89352455891786e-03f);
    float num = __fmul_rn(xc, np);
    float dp = fmaf(x2, 1.19825839466702e-06f, 1.18534705686654e-04f);
    dp = fmaf(x2, dp, 2.26843463243900e-03f);
    dp = fmaf(x2, dp, 4.89352518554385e-03f);
    float r = __fdiv_rn(num, dp);
    return (fabsf(x) < 0.0004f) ? x : r;
}
__device__ __forceinline__ float xla_sigmoid(float x)
{
    return __fadd_rn(0.5f, __fmul_rn(0.5f, xla_tanh(__fmul_rn(0.5f, x))));
}

// ---------------------------------------------------------------------------
// Transpose W2 for coalesced access in msg_exact
__global__ void prep_kernel(const float* __restrict__ Wmsg)
{
    int t = blockIdx.x * blockDim.x + threadIdx.x;
    if (t >= 256 * 256) return;
    int k = t >> 8, r = t & 255;
    g_W2T[k * 256 + r] = Wmsg[r * 512 + 256 + k];
}

// ---------------------------------------------------------------------------
// x = emb[perm]; h0=c0=x; write lstm_emb output; zero anchor-node message rows
__global__ void gather_init(const float* __restrict__ emb,
                            const int* __restrict__ perm,
                            float* __restrict__ out_lstm_emb)
{
    int gid = blockIdx.x * blockDim.x + threadIdx.x;
    if (gid >= CNH) return;
    int n = gid >> 8, h = gid & 255;
    float v = emb[(size_t)perm[n] * CH + h];
    g_x[gid] = v;
    out_lstm_emb[gid] = v;
    g_h[gid] = v;
    g_c[gid] = v;
    if (n % CK == 0) g_m[gid] = 0.f;   // node 0 never receives messages
}

// ---------------------------------------------------------------------------
// C[M,N] = A[M,K] @ B[N,K]^T. Each output is ONE sequential fma chain over k
// (k ascending) — association preserved exactly; FFMA2 lanes are bitwise
// identical to the scalar version.
// mode 0: acc starts at 0, store acc.
// mode 1: acc starts at 0, store acc + Cinit   (post-add)
// mode 2: acc starts at Cinit (chain prefix), store acc.
__global__ __launch_bounds__(256, 2) void sgemm_nt(
    int M, int N, int K,
    const float* __restrict__ A, int lda,
    const float* __restrict__ Bm, int ldb,
    float* __restrict__ C, int ldc,
    const float* __restrict__ Cinit, int mode)
{
    __shared__ float As[16][128];
    __shared__ float Bs[16][128];
    const int tid = threadIdx.x;
    const int tx = tid & 15;
    const int ty = tid >> 4;
    const float* Ab = A + (size_t)blockIdx.y * 128 * lda;
    const float* Bb = Bm + (size_t)blockIdx.x * 128 * ldb;

    u64 acc2[8][4];   // j-pairs: (0,1)(2,3)(4,5)(6,7)
    if (mode == 2) {
#pragma unroll
        for (int i = 0; i < 8; i++) {
            int lr = (i < 4) ? (ty * 4 + i) : (64 + ty * 4 + i - 4);
            size_t r = (size_t)blockIdx.y * 128 + lr;
            const float* Ir = Cinit + r * ldc + (size_t)blockIdx.x * 128;
            float4 c0 = *(const float4*)(Ir + tx * 4);
            float4 c1 = *(const float4*)(Ir + 64 + tx * 4);
            acc2[i][0] = pk2(c0.x, c0.y); acc2[i][1] = pk2(c0.z, c0.w);
            acc2[i][2] = pk2(c1.x, c1.y); acc2[i][3] = pk2(c1.z, c1.w);
        }
    } else {
#pragma unroll
        for (int i = 0; i < 8; i++)
#pragma unroll
            for (int j = 0; j < 4; j++) acc2[i][j] = 0ull;
    }

    const int lrow = tid >> 1;
    const int lk4b = (tid & 1) * 2;

    for (int kt = 0; kt < K; kt += 16) {
#pragma unroll
        for (int u = 0; u < 2; u++) {
            int k4 = lk4b + u;
            float4 av = *(const float4*)(Ab + (size_t)lrow * lda + kt + k4 * 4);
            As[k4 * 4 + 0][lrow] = av.x;
            As[k4 * 4 + 1][lrow] = av.y;
            As[k4 * 4 + 2][lrow] = av.z;
            As[k4 * 4 + 3][lrow] = av.w;
            float4 bv = *(const float4*)(Bb + (size_t)lrow * ldb + kt + k4 * 4);
            Bs[k4 * 4 + 0][lrow] = bv.x;
            Bs[k4 * 4 + 1][lrow] = bv.y;
            Bs[k4 * 4 + 2][lrow] = bv.z;
            Bs[k4 * 4 + 3][lrow] = bv.w;
        }
        __syncthreads();
#pragma unroll
        for (int k = 0; k < 16; k++) {
            float a[8], b[8];
            *(float4*)(a)     = *(const float4*)(&As[k][ty * 4]);
            *(float4*)(a + 4) = *(const float4*)(&As[k][64 + ty * 4]);
            *(float4*)(b)     = *(const float4*)(&Bs[k][tx * 4]);
            *(float4*)(b + 4) = *(const float4*)(&Bs[k][64 + tx * 4]);
            u64 b2[4] = { pk2(b[0], b[1]), pk2(b[2], b[3]),
                          pk2(b[4], b[5]), pk2(b[6], b[7]) };
#pragma unroll
            for (int i = 0; i < 8; i++) {
                u64 ad = pk2(a[i], a[i]);
#pragma unroll
                for (int j = 0; j < 4; j++)
                    acc2[i][j] = ffma2(ad, b2[j], acc2[i][j]);
            }
        }
        __syncthreads();
    }

#pragma unroll
    for (int i = 0; i < 8; i++) {
        int lr = (i < 4) ? (ty * 4 + i) : (64 + ty * 4 + i - 4);
        size_t r = (size_t)blockIdx.y * 128 + lr;
        float* Cr = C + r * ldc + (size_t)blockIdx.x * 128;
        float2 p0 = up2(acc2[i][0]), p1 = up2(acc2[i][1]);
        float2 p2 = up2(acc2[i][2]), p3 = up2(acc2[i][3]);
        float4 v0 = make_float4(p0.x, p0.y, p1.x, p1.y);
        float4 v1 = make_float4(p2.x, p2.y, p3.x, p3.y);
        if (mode == 1) {
            const float* Ir = Cinit + r * ldc + (size_t)blockIdx.x * 128;
            float4 c0 = *(const float4*)(Ir + tx * 4);
            float4 c1 = *(const float4*)(Ir + 64 + tx * 4);
            v0.x = __fadd_rn(v0.x, c0.x); v0.y = __fadd_rn(v0.y, c0.y);
            v0.z = __fadd_rn(v0.z, c0.z); v0.w = __fadd_rn(v0.w, c0.w);
            v1.x = __fadd_rn(v1.x, c1.x); v1.y = __fadd_rn(v1.y, c1.y);
            v1.z = __fadd_rn(v1.z, c1.z); v1.w = __fadd_rn(v1.w, c1.w);
        }
        *(float4*)(Cr + tx * 4) = v0;
        *(float4*)(Cr + 64 + tx * 4) = v1;
    }
}

// ---------------------------------------------------------------------------
// Exact per-edge msg chains, FFMA2 version. Block = (dst j, board b);
// 128 threads, thread rh handles outputs r = 2rh and 2rh+1.
// Edge (i -> j): acc starts at A_i[r], then continues the SAME fma chain over
// the h_dst terms (k ascending). m_j[r] = sum over ascending i != j of relu.
__global__ __launch_bounds__(128) void msg_exact()
{
    __shared__ float hj[256];
    const int j = blockIdx.x;          // dst 0..23 -> node base+j
    const int b = blockIdx.y;
    const int base = b * CK + 1;
    const int rh = threadIdx.x;        // 0..127

    hj[rh]       = g_h[(size_t)(base + j) * CH + rh];
    hj[rh + 128] = g_h[(size_t)(base + j) * CH + rh + 128];
    __syncthreads();

    u64 acc[24];
#pragma unroll
    for (int i = 0; i < 24; i++)
        acc[i] = *(const u64*)(&g_A[(size_t)(base + i) * CH + 2 * rh]);

    const u64* w2p = (const u64*)g_W2T + rh;   // row k at offset k*128
#pragma unroll 4
    for (int k = 0; k < 256; k++) {
        u64 w = w2p[(size_t)k * 128];
        float hk = hj[k];
        u64 h2 = pk2(hk, hk);
#pragma unroll
        for (int i = 0; i < 24; i++)
            acc[i] = ffma2(h2, w, acc[i]);
    }

    float mlo = 0.f, mhi = 0.f;
#pragma unroll
    for (int i = 0; i < 24; i++)
        if (i != j) {
            float2 e = up2(acc[i]);
            mlo = __fadd_rn(mlo, fmaxf(e.x, 0.f));
            mhi = __fadd_rn(mhi, fmaxf(e.y, 0.f));
        }
    *(float2*)(&g_m[(size_t)(base + j) * CH + 2 * rh]) = make_float2(mlo, mhi);
}

// ---------------------------------------------------------------------------
// LSTM pointwise (explicit rn mul/add: XLA emits separate mul/add, no fma)
__global__ void lstm_step(float* __restrict__ hs_slice)
{
    int gid = blockIdx.x * blockDim.x + threadIdx.x;
    if (gid >= CNH) return;
    int n = gid >> 8, h = gid & 255;
    const float* g = g_gates + (size_t)n * 1024;
    float ig = g[h], fg = g[256 + h], gg = g[512 + h], og = g[768 + h];
    float c = g_c[gid];
    float si = xla_sigmoid(ig);
    float sf = xla_sigmoid(fg);
    float so = xla_sigmoid(og);
    float nc = __fadd_rn(__fmul_rn(sf, c), __fmul_rn(si, xla_tanh(gg)));
    float nh = __fmul_rn(so, xla_tanh(nc));
    g_c[gid] = nc;
    g_h[gid] = nh;
    hs_slice[gid] = nh;
}

// ---------------------------------------------------------------------------
// input_emb_out / output_emb_out assembly
__global__ void finalize_emb(float* __restrict__ o_in, float* __restrict__ o_out)
{
    int gid = blockIdx.x * blockDim.x + threadIdx.x;
    if (gid >= CNH) return;
    int n = gid >> 8;
    bool anchor = (n % CK) == 0;
    float xv = g_x[gid];
    float hv = g_h[gid];
    float ov = g_oe[gid];
    o_in[gid]  = anchor ? xv : hv;
    o_out[gid] = anchor ? xv : ov;
}

// ---------------------------------------------------------------------------
// avg_dot over one 24x256 group
__global__ __launch_bounds__(256) void gol_kernel(const float* __restrict__ src, int out_base)
{
    __shared__ float hn[24][257];
    __shared__ float nrm[24];
    __shared__ float red[256];
    const int tid = threadIdx.x;
    const size_t rowbase = (size_t)blockIdx.x * 25 + 1;
    for (int idx = tid; idx < 24 * 256; idx += 256) {
        int i = idx >> 8, k = idx & 255;
        hn[i][k] = src[(rowbase + i) * 256 + k];
    }
    __syncthreads();
    if (tid < 24) {
        float s = 0.f;
        for (int k = 0; k < 256; k++) { float v = hn[tid][k]; s += v * v; }
        nrm[tid] = 1.f / (sqrtf(s) + 1e-8f);
    }
    __syncthreads();
    for (int idx = tid; idx < 24 * 256; idx += 256) {
        int i = idx >> 8, k = idx & 255;
        hn[i][k] *= nrm[i];
    }
    __syncthreads();
    float local = 0.f;
    for (int p = tid; p < 276; p += 256) {
        int i = 0, pp = p;
        while (pp >= 23 - i) { pp -= 23 - i; i++; }
        int j = i + 1 + pp;
        float d = 0.f;
#pragma unroll 8
        for (int k = 0; k < 256; k++) d += hn[i][k] * hn[j][k];
        local += fabsf(d);
    }
    red[tid] = local;
    __syncthreads();
    for (int s = 128; s > 0; s >>= 1) {
        if (tid < s) red[tid] += red[tid + s];
        __syncthreads();
    }
    if (tid == 0) g_red[out_base + blockIdx.x] = red[0] * (2.f / (24.f * 23.f));
}

__global__ void gol_finalize(float* __restrict__ out)
{
    __shared__ double red[256];
    int tid = threadIdx.x;
    double s1 = 0.0, s2 = 0.0;
    for (int i = tid; i < CSTEPS * CB; i += 256) s1 += (double)g_red[i];
    for (int i = tid; i < CB; i += 256) s2 += (double)g_red[CSTEPS * CB + i];
    red[tid] = s1 / (double)(CSTEPS * CB) + s2 / (double)CB;
    __syncthreads();
    for (int s = 128; s > 0; s >>= 1) {
        if (tid < s) red[tid] += red[tid + s];
        __syncthreads();
    }
    if (tid == 0) out[0] = (float)red[0];
}

// ---------------------------------------------------------------------------
extern "C" void kernel_launch(void* const* d_in, const int* in_sizes, int n_in,
                              void* d_out, int out_size)
{
    (void)in_sizes; (void)n_in; (void)out_size;
    const float* emb  = (const float*)d_in[0];  // fixed_embeddings (65,256)
    const float* Wmsg = (const float*)d_in[1];  // (256,512)
    const float* Wih  = (const float*)d_in[2];  // (1024,512)
    const float* Whh  = (const float*)d_in[3];  // (1024,256)
    const float* Wout = (const float*)d_in[4];  // (256,256)
    const int*   perm = (const int*)d_in[5];    // (512,25)

    float* out = (float*)d_out;
    float* o_gol  = out;
    float* o_lstm = out + 1;
    float* o_in   = out + 1 + (size_t)CNH;
    float* o_out  = out + 1 + 2 * (size_t)CNH;
    float* o_hs   = out + 1 + 3 * (size_t)CNH;

    float *px, *ph, *pgx, *pA, *pm, *pgates, *poe;
    cudaGetSymbolAddress((void**)&px,     g_x);
    cudaGetSymbolAddress((void**)&ph,     g_h);
    cudaGetSymbolAddress((void**)&pgx,    g_gx);
    cudaGetSymbolAddress((void**)&pA,     g_A);
    cudaGetSymbolAddress((void**)&pm,     g_m);
    cudaGetSymbolAddress((void**)&pgates, g_gates);
    cudaGetSymbolAddress((void**)&poe,    g_oe);

    prep_kernel<<<256, 256>>>(Wmsg);
    gather_init<<<CNH / 256, 256>>>(emb, perm, o_lstm);

    // gx = x @ W_ih[:, :256]^T  — chain prefix of t1, bitwise reusable each step
    sgemm_nt<<<dim3(8, CN / 128), 256>>>(CN, 1024, 256, px, 256, Wih, 512,
                                         pgx, 1024, nullptr, 0);

    for (int s = 0; s < CSTEPS; s++) {
        // A = h @ W1^T  (edge-chain first half; W1 = Wmsg[:, :256], ldb=512)
        sgemm_nt<<<dim3(2, CN / 128), 256>>>(CN, 256, 256, ph, 256, Wmsg, 512,
                                             pA, 256, nullptr, 0);
        // per-edge chain continuation + relu + ascending-i sum
        msg_exact<<<dim3(24, CB), 128>>>();
        // t1 = [x|m]@W_ih^T == chain(m-part) with acc initialized to gx (mode 2)
        sgemm_nt<<<dim3(8, CN / 128), 256>>>(CN, 1024, 256, pm, 256, Wih + 256, 512,
                                             pgates, 1024, pgx, 2);
        // gates = t1 + t2, t2 = h@W_hh^T (full chain from 0, post-add t1; mode 1)
        sgemm_nt<<<dim3(8, CN / 128), 256>>>(CN, 1024, 256, ph, 256, Whh, 256,
                                             pgates, 1024, pgates, 1);
        lstm_step<<<CNH / 256, 256>>>(o_hs + (size_t)s * CNH);
    }

    // output_embeddings = h_last @ W_out^T
    sgemm_nt<<<dim3(2, CN / 128), 256>>>(CN, 256, 256, ph, 256, Wout, 256,
                                         poe, 256, nullptr, 0);
    finalize_emb<<<CNH / 256, 256>>>(o_in, o_out);

    gol_kernel<<<CSTEPS * CB, 256>>>(o_hs, 0);
    gol_kernel<<<CB, 256>>>(poe, CSTEPS * CB);
    gol_finalize<<<1, 256>>>(o_gol);
}

// round 8
// speedup vs baseline: 1.1419x; 1.0734x over previous
#include <cuda_runtime.h>
#include <math.h>

// Problem constants
constexpr int CB = 512;        // batch
constexpr int CK = 25;         // nodes per board (incl. anchor node 0)
constexpr int CH = 256;        // hidden
constexpr int CSTEPS = 32;
constexpr int CN = CB * CK;    // 12800 nodes
constexpr int CNH = CN * CH;   // 3276800

// Scratch (device globals; no allocation allowed)
__device__ float g_x[CNH];             // lstm_emb (constant x)
__device__ float g_h[CNH];             // hidden state
__device__ float g_c[CNH];             // cell state
__device__ float g_gx[CN * 1024];      // chain prefix: x @ W_ih[:, :256].T
__device__ float g_A[CNH];             // per-step A = h @ W1^T (edge-chain first half)
__device__ float g_m[CNH];             // per-step messages
__device__ float g_t2[CN * 1024];      // per-step t2 = h @ W_hh^T
__device__ float g_gates[CN * 1024];   // gates
__device__ float g_W2T[256 * 256];     // W2 transposed
__device__ float g_oe[CNH];            // output_embeddings
__device__ float g_red[CSTEPS * CB + CB];  // per-block gol partials

// ---------------------------------------------------------------------------
// Packed f32x2 helpers (Blackwell FFMA2) — bitwise identical per lane to scalar.
typedef unsigned long long u64;
__device__ __forceinline__ u64 pk2(float lo, float hi)
{
    u64 r; asm("mov.b64 %0, {%1, %2};" : "=l"(r) : "f"(lo), "f"(hi)); return r;
}
__device__ __forceinline__ float2 up2(u64 v)
{
    float2 f; asm("mov.b64 {%0, %1}, %2;" : "=f"(f.x), "=f"(f.y) : "l"(v)); return f;
}
__device__ __forceinline__ u64 ffma2(u64 a, u64 b, u64 c)
{
    u64 d; asm("fma.rn.f32x2 %0, %1, %2, %3;" : "=l"(d) : "l"(a), "l"(b), "l"(c));
    return d;
}

// ---------------------------------------------------------------------------
// XLA elementwise replicas (EmitFastTanh; logistic = 0.5 + 0.5*tanh(0.5x)).
__device__ __forceinline__ float xla_tanh(float x)
{
    float xc = fminf(fmaxf(x, -9.f), 9.f);
    float x2 = __fmul_rn(xc, xc);
    float np = fmaf(x2, -2.76076847742355e-16f, 2.00018790482477e-13f);
    np = fmaf(x2, np, -8.60467152213735e-11f);
    np = fmaf(x2, np,  5.12229709037114e-08f);
    np = fmaf(x2, np,  1.48572235717979e-05f);
    np = fmaf(x2, np,  6.37261928875436e-04f);
    np = fmaf(x2, np,  4.89352455891786e-03f);
    float num = __fmul_rn(xc, np);
    float dp = fmaf(x2, 1.19825839466702e-06f, 1.18534705686654e-04f);
    dp = fmaf(x2, dp, 2.26843463243900e-03f);
    dp = fmaf(x2, dp, 4.89352518554385e-03f);
    float r = __fdiv_rn(num, dp);
    return (fabsf(x) < 0.0004f) ? x : r;
}
__device__ __forceinline__ float xla_sigmoid(float x)
{
    return __fadd_rn(0.5f, __fmul_rn(0.5f, xla_tanh(__fmul_rn(0.5f, x))));
}

// ---------------------------------------------------------------------------
__global__ void prep_kernel(const float* __restrict__ Wmsg)
{
    int t = blockIdx.x * blockDim.x + threadIdx.x;
    if (t >= 256 * 256) return;
    int k = t >> 8, r = t & 255;
    g_W2T[k * 256 + r] = Wmsg[r * 512 + 256 + k];
}

// ---------------------------------------------------------------------------
__global__ void gather_init(const float* __restrict__ emb,
                            const int* __restrict__ perm,
                            float* __restrict__ out_lstm_emb)
{
    int gid = blockIdx.x * blockDim.x + threadIdx.x;
    if (gid >= CNH) return;
    int n = gid >> 8, h = gid & 255;
    float v = emb[(size_t)perm[n] * CH + h];
    g_x[gid] = v;
    out_lstm_emb[gid] = v;
    g_h[gid] = v;
    g_c[gid] = v;
    if (n % CK == 0) g_m[gid] = 0.f;   // node 0 never receives messages
}

// ---------------------------------------------------------------------------
// GEMM tile body: C[128,128 @ (by,bx)] = A[M,K] @ B[N,K]^T.
// One sequential fma chain over ascending k per output (association preserved
// exactly; FFMA2 lanes bitwise == scalar). Register double-buffered pipeline,
// one __syncthreads per k-tile.
// Cinit != null : acc starts at Cinit (chain prefix).
// Cadd  != null : store acc + Cadd (post-add; commutative).
__device__ __forceinline__ void sgemm_tile(
    int K,
    const float* __restrict__ A, int lda,
    const float* __restrict__ Bm, int ldb,
    float* __restrict__ C, int ldc,
    const float* __restrict__ Cinit,
    const float* __restrict__ Cadd,
    int bx, int by,
    float As[2][16][128], float Bs[2][16][128])
{
    const int tid = threadIdx.x;
    const int tx = tid & 15;
    const int ty = tid >> 4;
    const float* Ab = A + (size_t)by * 128 * lda;
    const float* Bb = Bm + (size_t)bx * 128 * ldb;
    const int lrow = tid >> 1;
    const int lk4b = (tid & 1) * 2;

    u64 acc2[8][4];   // j-pairs: (0,1)(2,3)(4,5)(6,7)
    if (Cinit) {
#pragma unroll
        for (int i = 0; i < 8; i++) {
            int lr = (i < 4) ? (ty * 4 + i) : (64 + ty * 4 + i - 4);
            size_t r = (size_t)by * 128 + lr;
            const float* Ir = Cinit + r * ldc + (size_t)bx * 128;
            float4 c0 = *(const float4*)(Ir + tx * 4);
            float4 c1 = *(const float4*)(Ir + 64 + tx * 4);
            acc2[i][0] = pk2(c0.x, c0.y); acc2[i][1] = pk2(c0.z, c0.w);
            acc2[i][2] = pk2(c1.x, c1.y); acc2[i][3] = pk2(c1.z, c1.w);
        }
    } else {
#pragma unroll
        for (int i = 0; i < 8; i++)
#pragma unroll
            for (int j = 0; j < 4; j++) acc2[i][j] = 0ull;
    }

    float4 avs[2], bvs[2];
#pragma unroll
    for (int u = 0; u < 2; u++) {
        int k4 = lk4b + u;
        avs[u] = *(const float4*)(Ab + (size_t)lrow * lda + k4 * 4);
        bvs[u] = *(const float4*)(Bb + (size_t)lrow * ldb + k4 * 4);
    }
#pragma unroll
    for (int u = 0; u < 2; u++) {
        int k4 = lk4b + u;
        As[0][k4 * 4 + 0][lrow] = avs[u].x;
        As[0][k4 * 4 + 1][lrow] = avs[u].y;
        As[0][k4 * 4 + 2][lrow] = avs[u].z;
        As[0][k4 * 4 + 3][lrow] = avs[u].w;
        Bs[0][k4 * 4 + 0][lrow] = bvs[u].x;
        Bs[0][k4 * 4 + 1][lrow] = bvs[u].y;
        Bs[0][k4 * 4 + 2][lrow] = bvs[u].z;
        Bs[0][k4 * 4 + 3][lrow] = bvs[u].w;
    }
    __syncthreads();

    const int T = K >> 4;
    int buf = 0;
    for (int t = 0; t < T; t++) {
        if (t + 1 < T) {
            int kt = (t + 1) * 16;
#pragma unroll
            for (int u = 0; u < 2; u++) {
                int k4 = lk4b + u;
                avs[u] = *(const float4*)(Ab + (size_t)lrow * lda + kt + k4 * 4);
                bvs[u] = *(const float4*)(Bb + (size_t)lrow * ldb + kt + k4 * 4);
            }
        }
#pragma unroll
        for (int k = 0; k < 16; k++) {
            float a[8], b[8];
            *(float4*)(a)     = *(const float4*)(&As[buf][k][ty * 4]);
            *(float4*)(a + 4) = *(const float4*)(&As[buf][k][64 + ty * 4]);
            *(float4*)(b)     = *(const float4*)(&Bs[buf][k][tx * 4]);
            *(float4*)(b + 4) = *(const float4*)(&Bs[buf][k][64 + tx * 4]);
            u64 b2[4] = { pk2(b[0], b[1]), pk2(b[2], b[3]),
                          pk2(b[4], b[5]), pk2(b[6], b[7]) };
#pragma unroll
            for (int i = 0; i < 8; i++) {
                u64 ad = pk2(a[i], a[i]);
#pragma unroll
                for (int j = 0; j < 4; j++)
                    acc2[i][j] = ffma2(ad, b2[j], acc2[i][j]);
            }
        }
        if (t + 1 < T) {
            int nb = buf ^ 1;
#pragma unroll
            for (int u = 0; u < 2; u++) {
                int k4 = lk4b + u;
                As[nb][k4 * 4 + 0][lrow] = avs[u].x;
                As[nb][k4 * 4 + 1][lrow] = avs[u].y;
                As[nb][k4 * 4 + 2][lrow] = avs[u].z;
                As[nb][k4 * 4 + 3][lrow] = avs[u].w;
                Bs[nb][k4 * 4 + 0][lrow] = bvs[u].x;
                Bs[nb][k4 * 4 + 1][lrow] = bvs[u].y;
                Bs[nb][k4 * 4 + 2][lrow] = bvs[u].z;
                Bs[nb][k4 * 4 + 3][lrow] = bvs[u].w;
            }
            __syncthreads();
            buf = nb;
        }
    }

#pragma unroll
    for (int i = 0; i < 8; i++) {
        int lr = (i < 4) ? (ty * 4 + i) : (64 + ty * 4 + i - 4);
        size_t r = (size_t)by * 128 + lr;
        float* Cr = C + r * ldc + (size_t)bx * 128;
        float2 p0 = up2(acc2[i][0]), p1 = up2(acc2[i][1]);
        float2 p2 = up2(acc2[i][2]), p3 = up2(acc2[i][3]);
        float4 v0 = make_float4(p0.x, p0.y, p1.x, p1.y);
        float4 v1 = make_float4(p2.x, p2.y, p3.x, p3.y);
        if (Cadd) {
            const float* Ir = Cadd + r * ldc + (size_t)bx * 128;
            float4 c0 = *(const float4*)(Ir + tx * 4);
            float4 c1 = *(const float4*)(Ir + 64 + tx * 4);
            v0.x = __fadd_rn(v0.x, c0.x); v0.y = __fadd_rn(v0.y, c0.y);
            v0.z = __fadd_rn(v0.z, c0.z); v0.w = __fadd_rn(v0.w, c0.w);
            v1.x = __fadd_rn(v1.x, c1.x); v1.y = __fadd_rn(v1.y, c1.y);
            v1.z = __fadd_rn(v1.z, c1.z); v1.w = __fadd_rn(v1.w, c1.w);
        }
        *(float4*)(Cr + tx * 4) = v0;
        *(float4*)(Cr + 64 + tx * 4) = v1;
    }
}

__global__ __launch_bounds__(256, 2) void sgemm_nt(
    int K,
    const float* __restrict__ A, int lda,
    const float* __restrict__ Bm, int ldb,
    float* __restrict__ C, int ldc,
    const float* __restrict__ Cinit,
    const float* __restrict__ Cadd)
{
    __shared__ float As[2][16][128];
    __shared__ float Bs[2][16][128];
    sgemm_tile(K, A, lda, Bm, ldb, C, ldc, Cinit, Cadd,
               blockIdx.x, blockIdx.y, As, Bs);
}

// Fused pre-msg launch: blocks 0..799 compute t2 = h @ W_hh^T (8x100 tiles),
// blocks 800..999 compute A = h @ W1^T (2x100 tiles). Both depend only on h.
__global__ __launch_bounds__(256, 2) void step_pre(
    const float* __restrict__ Whh, const float* __restrict__ Wmsg)
{
    __shared__ float As[2][16][128];
    __shared__ float Bs[2][16][128];
    int bid = blockIdx.x;
    if (bid < 800) {
        sgemm_tile(256, g_h, 256, Whh, 256, g_t2, 1024, nullptr, nullptr,
                   bid & 7, bid >> 3, As, Bs);
    } else {
        int i = bid - 800;
        sgemm_tile(256, g_h, 256, Wmsg, 512, g_A, 256, nullptr, nullptr,
                   i & 1, i >> 1, As, Bs);
    }
}

// ---------------------------------------------------------------------------
// Exact per-edge msg chains, FFMA2 (at the FFMA2 issue floor).
__global__ __launch_bounds__(128) void msg_exact()
{
    __shared__ float hj[256];
    const int j = blockIdx.x;
    const int b = blockIdx.y;
    const int base = b * CK + 1;
    const int rh = threadIdx.x;

    hj[rh]       = g_h[(size_t)(base + j) * CH + rh];
    hj[rh + 128] = g_h[(size_t)(base + j) * CH + rh + 128];
    __syncthreads();

    u64 acc[24];
#pragma unroll
    for (int i = 0; i < 24; i++)
        acc[i] = *(const u64*)(&g_A[(size_t)(base + i) * CH + 2 * rh]);

    const u64* w2p = (const u64*)g_W2T + rh;
#pragma unroll 4
    for (int k = 0; k < 256; k++) {
        u64 w = w2p[(size_t)k * 128];
        float hk = hj[k];
        u64 h2 = pk2(hk, hk);
#pragma unroll
        for (int i = 0; i < 24; i++)
            acc[i] = ffma2(h2, w, acc[i]);
    }

    float mlo = 0.f, mhi = 0.f;
#pragma unroll
    for (int i = 0; i < 24; i++)
        if (i != j) {
            float2 e = up2(acc[i]);
            mlo = __fadd_rn(mlo, fmaxf(e.x, 0.f));
            mhi = __fadd_rn(mhi, fmaxf(e.y, 0.f));
        }
    *(float2*)(&g_m[(size_t)(base + j) * CH + 2 * rh]) = make_float2(mlo, mhi);
}

// ---------------------------------------------------------------------------
__global__ void lstm_step(float* __restrict__ hs_slice)
{
    int gid = blockIdx.x * blockDim.x + threadIdx.x;
    if (gid >= CNH) return;
    int n = gid >> 8, h = gid & 255;
    const float* g = g_gates + (size_t)n * 1024;
    float ig = g[h], fg = g[256 + h], gg = g[512 + h], og = g[768 + h];
    float c = g_c[gid];
    float si = xla_sigmoid(ig);
    float sf = xla_sigmoid(fg);
    float so = xla_sigmoid(og);
    float nc = __fadd_rn(__fmul_rn(sf, c), __fmul_rn(si, xla_tanh(gg)));
    float nh = __fmul_rn(so, xla_tanh(nc));
    g_c[gid] = nc;
    g_h[gid] = nh;
    hs_slice[gid] = nh;
}

// ---------------------------------------------------------------------------
__global__ void finalize_emb(float* __restrict__ o_in, float* __restrict__ o_out)
{
    int gid = blockIdx.x * blockDim.x + threadIdx.x;
    if (gid >= CNH) return;
    int n = gid >> 8;
    bool anchor = (n % CK) == 0;
    float xv = g_x[gid];
    float hv = g_h[gid];
    float ov = g_oe[gid];
    o_in[gid]  = anchor ? xv : hv;
    o_out[gid] = anchor ? xv : ov;
}

// ---------------------------------------------------------------------------
__global__ __launch_bounds__(256) void gol_kernel(const float* __restrict__ src, int out_base)
{
    __shared__ float hn[24][257];
    __shared__ float nrm[24];
    __shared__ float red[256];
    const int tid = threadIdx.x;
    const size_t rowbase = (size_t)blockIdx.x * 25 + 1;
    for (int idx = tid; idx < 24 * 256; idx += 256) {
        int i = idx >> 8, k = idx & 255;
        hn[i][k] = src[(rowbase + i) * 256 + k];
    }
    __syncthreads();
    if (tid < 24) {
        float s = 0.f;
        for (int k = 0; k < 256; k++) { float v = hn[tid][k]; s += v * v; }
        nrm[tid] = 1.f / (sqrtf(s) + 1e-8f);
    }
    __syncthreads();
    for (int idx = tid; idx < 24 * 256; idx += 256) {
        int i = idx >> 8, k = idx & 255;
        hn[i][k] *= nrm[i];
    }
    __syncthreads();
    float local = 0.f;
    for (int p = tid; p < 276; p += 256) {
        int i = 0, pp = p;
        while (pp >= 23 - i) { pp -= 23 - i; i++; }
        int j = i + 1 + pp;
        float d = 0.f;
#pragma unroll 8
        for (int k = 0; k < 256; k++) d += hn[i][k] * hn[j][k];
        local += fabsf(d);
    }
    red[tid] = local;
    __syncthreads();
    for (int s = 128; s > 0; s >>= 1) {
        if (tid < s) red[tid] += red[tid + s];
        __syncthreads();
    }
    if (tid == 0) g_red[out_base + blockIdx.x] = red[0] * (2.f / (24.f * 23.f));
}

__global__ void gol_finalize(float* __restrict__ out)
{
    __shared__ double red[256];
    int tid = threadIdx.x;
    double s1 = 0.0, s2 = 0.0;
    for (int i = tid; i < CSTEPS * CB; i += 256) s1 += (double)g_red[i];
    for (int i = tid; i < CB; i += 256) s2 += (double)g_red[CSTEPS * CB + i];
    red[tid] = s1 / (double)(CSTEPS * CB) + s2 / (double)CB;
    __syncthreads();
    for (int s = 128; s > 0; s >>= 1) {
        if (tid < s) red[tid] += red[tid + s];
        __syncthreads();
    }
    if (tid == 0) out[0] = (float)red[0];
}

// ---------------------------------------------------------------------------
extern "C" void kernel_launch(void* const* d_in, const int* in_sizes, int n_in,
                              void* d_out, int out_size)
{
    (void)in_sizes; (void)n_in; (void)out_size;
    const float* emb  = (const float*)d_in[0];
    const float* Wmsg = (const float*)d_in[1];
    const float* Wih  = (const float*)d_in[2];
    const float* Whh  = (const float*)d_in[3];
    const float* Wout = (const float*)d_in[4];
    const int*   perm = (const int*)d_in[5];

    float* out = (float*)d_out;
    float* o_gol  = out;
    float* o_lstm = out + 1;
    float* o_in   = out + 1 + (size_t)CNH;
    float* o_out  = out + 1 + 2 * (size_t)CNH;
    float* o_hs   = out + 1 + 3 * (size_t)CNH;

    float *px, *ph, *pgx, *pm, *pt2, *pgates, *poe;
    cudaGetSymbolAddress((void**)&px,     g_x);
    cudaGetSymbolAddress((void**)&ph,     g_h);
    cudaGetSymbolAddress((void**)&pgx,    g_gx);
    cudaGetSymbolAddress((void**)&pm,     g_m);
    cudaGetSymbolAddress((void**)&pt2,    g_t2);
    cudaGetSymbolAddress((void**)&pgates, g_gates);
    cudaGetSymbolAddress((void**)&poe,    g_oe);

    prep_kernel<<<256, 256>>>(Wmsg);
    gather_init<<<CNH / 256, 256>>>(emb, perm, o_lstm);

    // gx = x @ W_ih[:, :256]^T  — chain prefix of t1, reused every step
    sgemm_nt<<<dim3(8, CN / 128), 256>>>(256, px, 256, Wih, 512,
                                         pgx, 1024, nullptr, nullptr);

    for (int s = 0; s < CSTEPS; s++) {
        // fused: t2 = h @ W_hh^T  AND  A = h @ W1^T  (both depend only on h)
        step_pre<<<1000, 256>>>(Whh, Wmsg);
        // per-edge exact msg chains
        msg_exact<<<dim3(24, CB), 128>>>();
        // gates = chain(gx -> m terms) + t2   (post-add, commutative)
        sgemm_nt<<<dim3(8, CN / 128), 256>>>(256, pm, 256, Wih + 256, 512,
                                             pgates, 1024, pgx, pt2);
        lstm_step<<<CNH / 256, 256>>>(o_hs + (size_t)s * CNH);
    }

    // output_embeddings = h_last @ W_out^T
    sgemm_nt<<<dim3(2, CN / 128), 256>>>(256, ph, 256, Wout, 256,
                                         poe, 256, nullptr, nullptr);
    finalize_emb<<<CNH / 256, 256>>>(o_in, o_out);

    gol_kernel<<<CSTEPS * CB, 256>>>(o_hs, 0);
    gol_kernel<<<CB, 256>>>(poe, CSTEPS * CB);
    gol_finalize<<<1, 256>>>(o_gol);
}